// round 14
// baseline (speedup 1.0000x reference)
#include <cuda_runtime.h>
#include <cuda_bf16.h>
#include <cstddef>
#include <cstdint>

// Problem constants
#define SS 2048
#define BB 64
#define DD 128
#define HH 128
#define GG 512   // 4*H

// 256 MB scratch for precomputed input gates: pre[t][b][512] = x@W_ih^T + b
__device__ float g_pre[(size_t)SS * BB * GG];

typedef unsigned long long ull;

// Packed fp32x2 ops (sm_100+)
#define FMA_F32X2(d, a, b, c) \
    asm("fma.rn.f32x2 %0, %1, %2, %3;" : "=l"(d) : "l"(a), "l"(b), "l"(c))
#define ADD_F32X2(d, a, b) \
    asm("add.rn.f32x2 %0, %1, %2;" : "=l"(d) : "l"(a), "l"(b))
#define UNPACK2(lo, hi, in) \
    asm("mov.b64 {%0, %1}, %2;" : "=f"(lo), "=f"(hi) : "l"(in))
// Single-instruction tanh (MUFU.TANH, sm_75+)
#define TANH_APPROX(d, x) \
    asm("tanh.approx.f32 %0, %1;" : "=f"(d) : "f"(x))
// fp32 -> tf32 bits (round to nearest)
#define CVT_TF32(out, in) \
    asm("cvt.rna.tf32.f32 %0, %1;" : "=r"(out) : "f"(in))

// ---------------------------------------------------------------------------
// Kernel P: pre = X @ W_ih^T + bias via tf32 mma.sync.m16n8k8.
// R14 delta: float4-vectorized staging (16x LDG.128 per matrix instead of
// 64x LDG.32) — cuts ~200 staging instrs/thread on a DRAM-bound kernel.
// ---------------------------------------------------------------------------
__global__ void __launch_bounds__(256) pre_gemm_kernel(
    const float* __restrict__ X,
    const float* __restrict__ Wih,
    const float* __restrict__ bias)
{
    extern __shared__ uint32_t smP[];
    uint32_t* As = smP;                 // 16384 u32 = 64 KB
    uint32_t* Bs = smP + 16384;         // 16384 u32 = 64 KB

    const int tid  = threadIdx.x;
    const int row0 = blockIdx.x * 128;
    const int col0 = blockIdx.y * 128;

    // ---- stage A (X tile): float4 loads, tf32 convert, fragment scatter ----
    #pragma unroll
    for (int it = 0; it < 16; it++) {
        int fidx = it * 256 + tid;       // 0..4095 float4s
        int m  = fidx >> 5;              // row within tile (32 float4/row)
        int k4 = fidx & 31;
        int k  = k4 * 4;
        float4 v = *(const float4*)&X[(size_t)(row0 + m) * DD + k];
        int w  = m >> 4, mr = m & 15;
        int k8 = k >> 3;
        int jhi = ((k & 7) >> 2) << 1;               // 0 or 2 for this quad
        int j0  = (mr >> 3) | jhi;                   // same j for all 4
        int lbase = ((mr & 7) << 2);                 // lane = lbase + (kc&3)
        uint32_t* dst = &As[((w * 16 + k8) * 32 + lbase) * 4 + j0];
        uint32_t t0, t1, t2, t3;
        CVT_TF32(t0, v.x); CVT_TF32(t1, v.y);
        CVT_TF32(t2, v.z); CVT_TF32(t3, v.w);
        dst[0]  = t0;   // lane+0
        dst[4]  = t1;   // lane+1
        dst[8]  = t2;   // lane+2
        dst[12] = t3;   // lane+3
    }
    // ---- stage B (Wih tile): same scheme ----
    #pragma unroll
    for (int it = 0; it < 16; it++) {
        int fidx = it * 256 + tid;
        int n  = fidx >> 5;
        int k4 = fidx & 31;
        int k  = k4 * 4;
        float4 v = *(const float4*)&Wih[(size_t)(col0 + n) * DD + k];
        int n8 = n >> 3, nc = n & 7;
        int k8 = k >> 3;
        int j0 = (k & 7) >> 2;                        // 0 or 1
        int lbase = nc << 2;
        uint32_t* dst = &Bs[((n8 * 16 + k8) * 32 + lbase) * 2 + j0];
        uint32_t t0, t1, t2, t3;
        CVT_TF32(t0, v.x); CVT_TF32(t1, v.y);
        CVT_TF32(t2, v.z); CVT_TF32(t3, v.w);
        dst[0] = t0;
        dst[2] = t1;
        dst[4] = t2;
        dst[6] = t3;
    }
    __syncthreads();

    const int warp = tid >> 5;
    const int lane = tid & 31;

    float c[16][4];
    #pragma unroll
    for (int n8 = 0; n8 < 16; n8++)
        #pragma unroll
        for (int j = 0; j < 4; j++) c[n8][j] = 0.0f;

    #pragma unroll 1
    for (int k8 = 0; k8 < 16; k8++) {
        uint4 af = *(const uint4*)&As[(((warp * 16 + k8) * 32) + lane) * 4];
        #pragma unroll
        for (int n8 = 0; n8 < 16; n8++) {
            uint2 bf = *(const uint2*)&Bs[(((n8 * 16 + k8) * 32) + lane) * 2];
            asm("mma.sync.aligned.m16n8k8.row.col.f32.tf32.tf32.f32 "
                "{%0,%1,%2,%3}, {%4,%5,%6,%7}, {%8,%9}, {%0,%1,%2,%3};"
                : "+f"(c[n8][0]), "+f"(c[n8][1]), "+f"(c[n8][2]), "+f"(c[n8][3])
                : "r"(af.x), "r"(af.y), "r"(af.z), "r"(af.w),
                  "r"(bf.x), "r"(bf.y));
        }
    }

    // ---- epilogue: bias + store ----
    const int ra = row0 + warp * 16 + (lane >> 2);
    const int cb = 2 * (lane & 3);
    #pragma unroll
    for (int n8 = 0; n8 < 16; n8++) {
        int col = col0 + n8 * 8 + cb;
        float2 bv = *(const float2*)&bias[col];
        float2 v0 = make_float2(c[n8][0] + bv.x, c[n8][1] + bv.y);
        float2 v1 = make_float2(c[n8][2] + bv.x, c[n8][3] + bv.y);
        *(float2*)&g_pre[(size_t)ra * GG + col]       = v0;
        *(float2*)&g_pre[(size_t)(ra + 8) * GG + col] = v1;
    }
}

// ---------------------------------------------------------------------------
// Cluster helpers
// ---------------------------------------------------------------------------
__device__ __forceinline__ uint32_t smem_u32(const void* p) {
    uint32_t a;
    asm("{ .reg .u64 t; cvta.to.shared.u64 t, %1; cvt.u32.u64 %0, t; }"
        : "=r"(a) : "l"(p));
    return a;
}
__device__ __forceinline__ uint32_t my_ctarank() {
    uint32_t r;
    asm("mov.u32 %0, %%cluster_ctarank;" : "=r"(r));
    return r;
}
__device__ __forceinline__ uint32_t mapa_u32(uint32_t local, uint32_t rank) {
    uint32_t r;
    asm("mapa.shared::cluster.u32 %0, %1, %2;" : "=r"(r) : "r"(local), "r"(rank));
    return r;
}
__device__ __forceinline__ void mbar_init(uint32_t addr, uint32_t count) {
    asm volatile("mbarrier.init.shared.b64 [%0], %1;"
                 :: "r"(addr), "r"(count) : "memory");
}
// Async store with HW transaction tracking (data + signal, no fences).
__device__ __forceinline__ void st_async_f32(uint32_t dst, float v, uint32_t mbar) {
    asm volatile(
        "st.async.shared::cluster.mbarrier::complete_tx::bytes.b32 [%0], %1, [%2];"
        :: "r"(dst), "r"(__float_as_uint(v)), "r"(mbar) : "memory");
}
__device__ __forceinline__ void mbar_expect_tx(uint32_t mbar, uint32_t bytes) {
    asm volatile("mbarrier.arrive.expect_tx.shared.b64 _, [%0], %1;"
                 :: "r"(mbar), "r"(bytes) : "memory");
}
__device__ __forceinline__ void mbar_wait(uint32_t mbar, uint32_t parity) {
    asm volatile(
        "{\n\t"
        ".reg .pred P;\n"
        "WL_%=:\n\t"
        "mbarrier.try_wait.parity.acquire.cta.shared::cta.b64 P, [%0], %1, 0x989680;\n\t"
        "@P bra WD_%=;\n\t"
        "bra WL_%=;\n"
        "WD_%=:\n\t"
        "}"
        :: "r"(mbar), "r"(parity) : "memory");
}
__device__ __forceinline__ void cluster_sync_hw() {
    asm volatile("barrier.cluster.arrive.aligned;" ::: "memory");
    asm volatile("barrier.cluster.wait.aligned;" ::: "memory");
}

// ---------------------------------------------------------------------------
// Kernel R: reverse scan, one 2-CTA CLUSTER per batch element.
// rank0 owns gate rows 0:256 (i,f); rank1 owns 256:512 (g,o). 256 thr/CTA,
// ALL 128 W_hh weights per thread register-resident.
// R14 delta vs R13/R10: the pre-wait __syncthreads is removed — local acts
// travel via st.async to the OWN CTA as well (R8 mechanism, proven), so the
// single mbar wait (expect 2048 B = both CTAs' 256 floats) covers local +
// peer visibility. Hoisted decay kept. One __syncthreads per step remains.
// ---------------------------------------------------------------------------
__global__ void __launch_bounds__(256, 1) __cluster_dims__(2, 1, 1)
lstm_rev_cluster_kernel(
    const float* __restrict__ timeArr,   // [S*B]
    const float* __restrict__ Whh,       // [512,128]
    const float* __restrict__ w_t,       // [128]
    const float* __restrict__ b_t,       // [128]
    float* __restrict__ out)             // outputs ++ h ++ c
{
    __shared__ __align__(16) float hbuf[2][128];
    __shared__ float act_all[2][512];
    __shared__ ull   mbars[2];

    const int tid   = threadIdx.x;
    const uint32_t rank  = my_ctarank();
    const uint32_t prank = 1u - rank;
    const int batch = blockIdx.x >> 1;
    const int grow  = (int)rank * 256 + tid;   // global gate row

    // ALL weights register-resident: 64 ull = 128 floats
    ull wR[64];
    {
        const ull* wp = (const ull*)(Whh + (size_t)grow * HH);
        #pragma unroll
        for (int c = 0; c < 64; c++) wR[c] = wp[c];
    }

    // Cluster-space addresses: my act slot in BOTH CTAs + both mbars
    const uint32_t mb0_l = smem_u32(&mbars[0]);
    const uint32_t mb1_l = smem_u32(&mbars[1]);
    uint32_t dst_own[2], dst_peer[2], mb_own[2], mb_peer[2];
    #pragma unroll
    for (int m = 0; m < 2; m++) {
        uint32_t a = smem_u32(&act_all[m][grow]);
        dst_own[m]  = mapa_u32(a, rank);
        dst_peer[m] = mapa_u32(a, prank);
        uint32_t mb = (m == 0) ? mb0_l : mb1_l;
        mb_own[m]   = mapa_u32(mb, rank);
        mb_peer[m]  = mapa_u32(mb, prank);
    }

    if (tid == 0) {
        mbar_init(mb0_l, 1);
        mbar_init(mb1_l, 1);
        // pre-arm both barriers for steps 0 and 1 (512 floats = 2048 B each)
        mbar_expect_tx(mb0_l, 2048);
        mbar_expect_tx(mb1_l, 2048);
    }
    if (tid < 128) hbuf[0][tid] = 0.0f;

    const float wt = w_t[tid & 127];
    const float bt = b_t[tid & 127];
    float creg = 0.0f, hlast = 0.0f;

    __syncthreads();
    cluster_sync_hw();   // mbars init+armed visible cluster-wide

    const float* preP = g_pre + (size_t)batch * GG + grow;

    // depth-2 prefetch pipeline for pre/tv
    float pre_n1 = preP[(size_t)(SS - 1) * BB * GG];
    float tv_n1  = timeArr[(size_t)(SS - 1) * BB + batch];
    float pre_n2 = preP[(size_t)(SS - 2) * BB * GG];
    float tv_n2  = timeArr[(size_t)(SS - 2) * BB + batch];

    const bool  is_g     = (rank == 1) && (tid < 128);
    // tanh path: g-gate uses tanh(x) directly; sigmoid = 0.5*tanh(x/2)+0.5
    const float pre_mul  = is_g ? 1.0f : 0.5f;

    for (int s = 0; s < SS; s++) {
        const int t   = SS - 1 - s;
        const int cur = s & 1;
        const int m   = s & 1;
        const uint32_t par = (uint32_t)((s >> 1) & 1);

        const float pre_j = pre_n1;
        const float tv    = tv_n1;
        pre_n1 = pre_n2;
        tv_n1  = tv_n2;
        if (t >= 2) {   // prefetch two steps ahead
            pre_n2 = preP[(size_t)(t - 2) * BB * GG];
            tv_n2  = timeArr[(size_t)(t - 2) * BB + batch];
        }

        // dot: gates[grow] = pre + W_hh[grow].h  (weights in regs,
        // 8 independent accumulator chains)
        const ulonglong2* h2 = (const ulonglong2*)&hbuf[cur][0];
        ull ac[8];
        #pragma unroll
        for (int i = 0; i < 8; i++) ac[i] = 0ULL;
        #pragma unroll
        for (int i = 0; i < 8; i++) {
            ulonglong2 hva = h2[4 * i],     hvb = h2[4 * i + 1];
            ulonglong2 hvc = h2[4 * i + 2], hvd = h2[4 * i + 3];
            FMA_F32X2(ac[0], wR[8 * i],     hva.x, ac[0]);
            FMA_F32X2(ac[1], wR[8 * i + 1], hva.y, ac[1]);
            FMA_F32X2(ac[2], wR[8 * i + 2], hvb.x, ac[2]);
            FMA_F32X2(ac[3], wR[8 * i + 3], hvb.y, ac[3]);
            FMA_F32X2(ac[4], wR[8 * i + 4], hvc.x, ac[4]);
            FMA_F32X2(ac[5], wR[8 * i + 5], hvc.y, ac[5]);
            FMA_F32X2(ac[6], wR[8 * i + 6], hvd.x, ac[6]);
            FMA_F32X2(ac[7], wR[8 * i + 7], hvd.y, ac[7]);
        }
        ADD_F32X2(ac[0], ac[0], ac[1]);
        ADD_F32X2(ac[2], ac[2], ac[3]);
        ADD_F32X2(ac[4], ac[4], ac[5]);
        ADD_F32X2(ac[6], ac[6], ac[7]);
        ADD_F32X2(ac[0], ac[0], ac[2]);
        ADD_F32X2(ac[4], ac[4], ac[6]);
        ADD_F32X2(ac[0], ac[0], ac[4]);
        float lo, hi;
        UNPACK2(lo, hi, ac[0]);
        float gsum = pre_j + (lo + hi);

        // activation via single MUFU.TANH:
        //   g-gate: tanh(gsum);  others: sigmoid = 0.5*tanh(0.5*gsum)+0.5
        float th;
        TANH_APPROX(th, pre_mul * gsum);
        float a = is_g ? th : fmaf(0.5f, th, 0.5f);

        // publish act to BOTH CTAs via async stores (HW tx tracking);
        // the single wait below covers local + peer visibility (no bar)
        st_async_f32(dst_own[m],  a, mb_own[m]);
        st_async_f32(dst_peer[m], a, mb_peer[m]);

        // decay term hoisted off the post-wait critical path
        float cfd = 0.0f;
        if (tid < 128) {
            float dec = __expf(-fmaxf(tv * wt + bt, 0.0f));
            cfd = creg * dec;
        }

        mbar_wait(m ? mb1_l : mb0_l, par);  // all 512 acts visible
        if (tid == 0)  // re-arm this barrier for step s+2 (ordered before
            mbar_expect_tx(m ? mb1_l : mb0_l, 2048);  // s+1 sends by the
                                                      // end-of-step bar)
        if (tid < 128) {
            const float* A = &act_all[m][0];
            float iv = A[tid];
            float fv = A[128 + tid];
            float gv = A[256 + tid];
            float ov = A[384 + tid];
            creg = fv * cfd + iv * gv;      // dec already folded into cfd
            float tc;
            TANH_APPROX(tc, creg);
            float hv = ov * tc;
            hlast = hv;
            hbuf[cur ^ 1][tid] = hv;
            out[(size_t)t * (BB * HH) + (size_t)batch * HH + tid] = hv;
        }
        __syncthreads();   // h published; also orders re-arm before s+1 sends
    }

    // final state: h then c after the outputs block (rank0 only; rank1's
    // redundant out[] writes above are bit-identical so either may win)
    if (rank == 0 && tid < 128) {
        size_t base = (size_t)SS * BB * HH;
        out[base + (size_t)batch * HH + tid] = hlast;
        out[base + (size_t)BB * HH + (size_t)batch * HH + tid] = creg;
    }

    cluster_sync_hw();   // no early exit while peer ops in flight
}

// ---------------------------------------------------------------------------
// Launch
// ---------------------------------------------------------------------------
extern "C" void kernel_launch(void* const* d_in, const int* in_sizes, int n_in,
                              void* d_out, int out_size)
{
    const float* X    = (const float*)d_in[0];  // input  (S,B,D)
    const float* Tm   = (const float*)d_in[1];  // time   (S,B,1)
    const float* Wih  = (const float*)d_in[2];  // (4H, D)
    const float* Whh  = (const float*)d_in[3];  // (4H, H)
    const float* bias = (const float*)d_in[4];  // (4H,)
    const float* wt   = (const float*)d_in[5];  // (H,)
    const float* bt   = (const float*)d_in[6];  // (H,)
    float* out = (float*)d_out;

    const int smemP = 2 * 16384 * (int)sizeof(uint32_t);   // 131072 B
    cudaFuncSetAttribute(pre_gemm_kernel,
                         cudaFuncAttributeMaxDynamicSharedMemorySize, smemP);

    dim3 gridP((SS * BB) / 128, GG / 128);
    pre_gemm_kernel<<<gridP, 256, smemP>>>(X, Wih, bias);

    // 64 clusters of 2 CTAs (grid 128), 256 threads each
    lstm_rev_cluster_kernel<<<BB * 2, 256>>>(Tm, Whh, wt, bt, out);
}

// round 15
// speedup vs baseline: 1.0374x; 1.0374x over previous
#include <cuda_runtime.h>
#include <cuda_bf16.h>
#include <cstddef>
#include <cstdint>

// Problem constants
#define SS 2048
#define BB 64
#define DD 128
#define HH 128
#define GG 512   // 4*H

// 256 MB scratch for precomputed input gates: pre[t][b][512] = x@W_ih^T + b
__device__ float g_pre[(size_t)SS * BB * GG];

typedef unsigned long long ull;

// Packed fp32x2 ops (sm_100+)
#define FMA_F32X2(d, a, b, c) \
    asm("fma.rn.f32x2 %0, %1, %2, %3;" : "=l"(d) : "l"(a), "l"(b), "l"(c))
#define ADD_F32X2(d, a, b) \
    asm("add.rn.f32x2 %0, %1, %2;" : "=l"(d) : "l"(a), "l"(b))
#define UNPACK2(lo, hi, in) \
    asm("mov.b64 {%0, %1}, %2;" : "=f"(lo), "=f"(hi) : "l"(in))
// Single-instruction tanh (MUFU.TANH, sm_75+)
#define TANH_APPROX(d, x) \
    asm("tanh.approx.f32 %0, %1;" : "=f"(d) : "f"(x))
// fp32 -> tf32 bits (round to nearest)
#define CVT_TF32(out, in) \
    asm("cvt.rna.tf32.f32 %0, %1;" : "=r"(out) : "f"(in))

// ---------------------------------------------------------------------------
// Kernel P: pre = X @ W_ih^T + bias via tf32 mma.sync.m16n8k8.
// R15 delta: grid mapping swapped — blockIdx.x = col-block (4), blockIdx.y =
// row-block (1024). Consecutive CTAs now share the same X tile, so 3 of the
// 4 X passes hit L2 instead of DRAM (512 MB -> ~330 MB total traffic).
// ---------------------------------------------------------------------------
__global__ void __launch_bounds__(256) pre_gemm_kernel(
    const float* __restrict__ X,
    const float* __restrict__ Wih,
    const float* __restrict__ bias)
{
    extern __shared__ uint32_t smP[];
    uint32_t* As = smP;                 // 16384 u32 = 64 KB
    uint32_t* Bs = smP + 16384;         // 16384 u32 = 64 KB

    const int tid  = threadIdx.x;
    const int row0 = blockIdx.y * 128;   // row block (1024)
    const int col0 = blockIdx.x * 128;   // col block (4) — fastest-varying

    // ---- stage A (X tile): float4 loads, tf32 convert, fragment scatter ----
    #pragma unroll
    for (int it = 0; it < 16; it++) {
        int fidx = it * 256 + tid;       // 0..4095 float4s
        int m  = fidx >> 5;              // row within tile (32 float4/row)
        int k4 = fidx & 31;
        int k  = k4 * 4;
        float4 v = *(const float4*)&X[(size_t)(row0 + m) * DD + k];
        int w  = m >> 4, mr = m & 15;
        int k8 = k >> 3;
        int jhi = ((k & 7) >> 2) << 1;               // 0 or 2 for this quad
        int j0  = (mr >> 3) | jhi;                   // same j for all 4
        int lbase = ((mr & 7) << 2);                 // lane = lbase + (kc&3)
        uint32_t* dst = &As[((w * 16 + k8) * 32 + lbase) * 4 + j0];
        uint32_t t0, t1, t2, t3;
        CVT_TF32(t0, v.x); CVT_TF32(t1, v.y);
        CVT_TF32(t2, v.z); CVT_TF32(t3, v.w);
        dst[0]  = t0;   // lane+0
        dst[4]  = t1;   // lane+1
        dst[8]  = t2;   // lane+2
        dst[12] = t3;   // lane+3
    }
    // ---- stage B (Wih tile): same scheme ----
    #pragma unroll
    for (int it = 0; it < 16; it++) {
        int fidx = it * 256 + tid;
        int n  = fidx >> 5;
        int k4 = fidx & 31;
        int k  = k4 * 4;
        float4 v = *(const float4*)&Wih[(size_t)(col0 + n) * DD + k];
        int n8 = n >> 3, nc = n & 7;
        int k8 = k >> 3;
        int j0 = (k & 7) >> 2;                        // 0 or 1
        int lbase = nc << 2;
        uint32_t* dst = &Bs[((n8 * 16 + k8) * 32 + lbase) * 2 + j0];
        uint32_t t0, t1, t2, t3;
        CVT_TF32(t0, v.x); CVT_TF32(t1, v.y);
        CVT_TF32(t2, v.z); CVT_TF32(t3, v.w);
        dst[0] = t0;
        dst[2] = t1;
        dst[4] = t2;
        dst[6] = t3;
    }
    __syncthreads();

    const int warp = tid >> 5;
    const int lane = tid & 31;

    float c[16][4];
    #pragma unroll
    for (int n8 = 0; n8 < 16; n8++)
        #pragma unroll
        for (int j = 0; j < 4; j++) c[n8][j] = 0.0f;

    #pragma unroll 1
    for (int k8 = 0; k8 < 16; k8++) {
        uint4 af = *(const uint4*)&As[(((warp * 16 + k8) * 32) + lane) * 4];
        #pragma unroll
        for (int n8 = 0; n8 < 16; n8++) {
            uint2 bf = *(const uint2*)&Bs[(((n8 * 16 + k8) * 32) + lane) * 2];
            asm("mma.sync.aligned.m16n8k8.row.col.f32.tf32.tf32.f32 "
                "{%0,%1,%2,%3}, {%4,%5,%6,%7}, {%8,%9}, {%0,%1,%2,%3};"
                : "+f"(c[n8][0]), "+f"(c[n8][1]), "+f"(c[n8][2]), "+f"(c[n8][3])
                : "r"(af.x), "r"(af.y), "r"(af.z), "r"(af.w),
                  "r"(bf.x), "r"(bf.y));
        }
    }

    // ---- epilogue: bias + store ----
    const int ra = row0 + warp * 16 + (lane >> 2);
    const int cb = 2 * (lane & 3);
    #pragma unroll
    for (int n8 = 0; n8 < 16; n8++) {
        int col = col0 + n8 * 8 + cb;
        float2 bv = *(const float2*)&bias[col];
        float2 v0 = make_float2(c[n8][0] + bv.x, c[n8][1] + bv.y);
        float2 v1 = make_float2(c[n8][2] + bv.x, c[n8][3] + bv.y);
        *(float2*)&g_pre[(size_t)ra * GG + col]       = v0;
        *(float2*)&g_pre[(size_t)(ra + 8) * GG + col] = v1;
    }
}

// ---------------------------------------------------------------------------
// Cluster helpers
// ---------------------------------------------------------------------------
__device__ __forceinline__ uint32_t smem_u32(const void* p) {
    uint32_t a;
    asm("{ .reg .u64 t; cvta.to.shared.u64 t, %1; cvt.u32.u64 %0, t; }"
        : "=r"(a) : "l"(p));
    return a;
}
__device__ __forceinline__ uint32_t my_ctarank() {
    uint32_t r;
    asm("mov.u32 %0, %%cluster_ctarank;" : "=r"(r));
    return r;
}
__device__ __forceinline__ uint32_t mapa_u32(uint32_t local, uint32_t rank) {
    uint32_t r;
    asm("mapa.shared::cluster.u32 %0, %1, %2;" : "=r"(r) : "r"(local), "r"(rank));
    return r;
}
__device__ __forceinline__ void mbar_init(uint32_t addr, uint32_t count) {
    asm volatile("mbarrier.init.shared.b64 [%0], %1;"
                 :: "r"(addr), "r"(count) : "memory");
}
// Async store with HW transaction tracking (data + signal, no fences).
__device__ __forceinline__ void st_async_f32(uint32_t dst, float v, uint32_t mbar) {
    asm volatile(
        "st.async.shared::cluster.mbarrier::complete_tx::bytes.b32 [%0], %1, [%2];"
        :: "r"(dst), "r"(__float_as_uint(v)), "r"(mbar) : "memory");
}
__device__ __forceinline__ void mbar_expect_tx(uint32_t mbar, uint32_t bytes) {
    asm volatile("mbarrier.arrive.expect_tx.shared.b64 _, [%0], %1;"
                 :: "r"(mbar), "r"(bytes) : "memory");
}
__device__ __forceinline__ void mbar_wait(uint32_t mbar, uint32_t parity) {
    asm volatile(
        "{\n\t"
        ".reg .pred P;\n"
        "WL_%=:\n\t"
        "mbarrier.try_wait.parity.acquire.cta.shared::cta.b64 P, [%0], %1, 0x989680;\n\t"
        "@P bra WD_%=;\n\t"
        "bra WL_%=;\n"
        "WD_%=:\n\t"
        "}"
        :: "r"(mbar), "r"(parity) : "memory");
}
__device__ __forceinline__ void cluster_sync_hw() {
    asm volatile("barrier.cluster.arrive.aligned;" ::: "memory");
    asm volatile("barrier.cluster.wait.aligned;" ::: "memory");
}

// ---------------------------------------------------------------------------
// Kernel R: reverse scan, one 2-CTA CLUSTER per batch element (R10/R13
// winner, verbatim — R14's dual-st.async variant regressed and is reverted).
// rank0 owns gate rows 0:256 (i,f); rank1 owns 256:512 (g,o). 256 thr/CTA,
// ALL 128 W_hh weights per thread register-resident. STS local + st.async
// to peer; pre-wait __syncthreads publishes local acts under the peer
// DSMEM flight; hoisted decay off the post-wait tail.
// ---------------------------------------------------------------------------
__global__ void __launch_bounds__(256, 1) __cluster_dims__(2, 1, 1)
lstm_rev_cluster_kernel(
    const float* __restrict__ timeArr,   // [S*B]
    const float* __restrict__ Whh,       // [512,128]
    const float* __restrict__ w_t,       // [128]
    const float* __restrict__ b_t,       // [128]
    float* __restrict__ out)             // outputs ++ h ++ c
{
    __shared__ __align__(16) float hbuf[2][128];
    __shared__ float act_all[2][512];
    __shared__ ull   mbars[2];

    const int tid   = threadIdx.x;
    const uint32_t rank  = my_ctarank();
    const uint32_t prank = 1u - rank;
    const int batch = blockIdx.x >> 1;
    const int grow  = (int)rank * 256 + tid;   // global gate row

    // ALL weights register-resident: 64 ull = 128 floats
    ull wR[64];
    {
        const ull* wp = (const ull*)(Whh + (size_t)grow * HH);
        #pragma unroll
        for (int c = 0; c < 64; c++) wR[c] = wp[c];
    }

    // Cluster-space addresses: my act slot in the PEER CTA + peer's mbars
    const uint32_t mb0_l = smem_u32(&mbars[0]);
    const uint32_t mb1_l = smem_u32(&mbars[1]);
    uint32_t dst_peer[2], mb_peer[2];
    #pragma unroll
    for (int m = 0; m < 2; m++) {
        uint32_t a = smem_u32(&act_all[m][grow]);
        dst_peer[m] = mapa_u32(a, prank);
        uint32_t mb = (m == 0) ? mb0_l : mb1_l;
        mb_peer[m]  = mapa_u32(mb, prank);
    }

    if (tid == 0) {
        mbar_init(mb0_l, 1);
        mbar_init(mb1_l, 1);
        // pre-arm both barriers for steps 0 and 1 (peer's 256 floats each)
        mbar_expect_tx(mb0_l, 1024);
        mbar_expect_tx(mb1_l, 1024);
    }
    if (tid < 128) hbuf[0][tid] = 0.0f;

    const float wt = w_t[tid & 127];
    const float bt = b_t[tid & 127];
    float creg = 0.0f, hlast = 0.0f;

    __syncthreads();
    cluster_sync_hw();   // mbars init+armed visible cluster-wide

    const float* preP = g_pre + (size_t)batch * GG + grow;

    // depth-2 prefetch pipeline for pre/tv
    float pre_n1 = preP[(size_t)(SS - 1) * BB * GG];
    float tv_n1  = timeArr[(size_t)(SS - 1) * BB + batch];
    float pre_n2 = preP[(size_t)(SS - 2) * BB * GG];
    float tv_n2  = timeArr[(size_t)(SS - 2) * BB + batch];

    const bool  is_g     = (rank == 1) && (tid < 128);
    // tanh path: g-gate uses tanh(x) directly; sigmoid = 0.5*tanh(x/2)+0.5
    const float pre_mul  = is_g ? 1.0f : 0.5f;

    for (int s = 0; s < SS; s++) {
        const int t   = SS - 1 - s;
        const int cur = s & 1;
        const int m   = s & 1;
        const uint32_t par = (uint32_t)((s >> 1) & 1);

        const float pre_j = pre_n1;
        const float tv    = tv_n1;
        pre_n1 = pre_n2;
        tv_n1  = tv_n2;
        if (t >= 2) {   // prefetch two steps ahead
            pre_n2 = preP[(size_t)(t - 2) * BB * GG];
            tv_n2  = timeArr[(size_t)(t - 2) * BB + batch];
        }

        // dot: gates[grow] = pre + W_hh[grow].h  (weights in regs,
        // 8 independent accumulator chains)
        const ulonglong2* h2 = (const ulonglong2*)&hbuf[cur][0];
        ull ac[8];
        #pragma unroll
        for (int i = 0; i < 8; i++) ac[i] = 0ULL;
        #pragma unroll
        for (int i = 0; i < 8; i++) {
            ulonglong2 hva = h2[4 * i],     hvb = h2[4 * i + 1];
            ulonglong2 hvc = h2[4 * i + 2], hvd = h2[4 * i + 3];
            FMA_F32X2(ac[0], wR[8 * i],     hva.x, ac[0]);
            FMA_F32X2(ac[1], wR[8 * i + 1], hva.y, ac[1]);
            FMA_F32X2(ac[2], wR[8 * i + 2], hvb.x, ac[2]);
            FMA_F32X2(ac[3], wR[8 * i + 3], hvb.y, ac[3]);
            FMA_F32X2(ac[4], wR[8 * i + 4], hvc.x, ac[4]);
            FMA_F32X2(ac[5], wR[8 * i + 5], hvc.y, ac[5]);
            FMA_F32X2(ac[6], wR[8 * i + 6], hvd.x, ac[6]);
            FMA_F32X2(ac[7], wR[8 * i + 7], hvd.y, ac[7]);
        }
        ADD_F32X2(ac[0], ac[0], ac[1]);
        ADD_F32X2(ac[2], ac[2], ac[3]);
        ADD_F32X2(ac[4], ac[4], ac[5]);
        ADD_F32X2(ac[6], ac[6], ac[7]);
        ADD_F32X2(ac[0], ac[0], ac[2]);
        ADD_F32X2(ac[4], ac[4], ac[6]);
        ADD_F32X2(ac[0], ac[0], ac[4]);
        float lo, hi;
        UNPACK2(lo, hi, ac[0]);
        float gsum = pre_j + (lo + hi);

        // activation via single MUFU.TANH:
        //   g-gate: tanh(gsum);  others: sigmoid = 0.5*tanh(0.5*gsum)+0.5
        float th;
        TANH_APPROX(th, pre_mul * gsum);
        float a = is_g ? th : fmaf(0.5f, th, 0.5f);

        // publish act: plain STS locally, st.async to PEER only
        act_all[m][grow] = a;
        st_async_f32(dst_peer[m], a, mb_peer[m]);

        // decay term hoisted off the post-wait critical path
        float cfd = 0.0f;
        if (tid < 128) {
            float dec = __expf(-fmaxf(tv * wt + bt, 0.0f));
            cfd = creg * dec;
        }

        __syncthreads();                    // local acts visible (overlaps
                                            // the peer DSMEM flight)
        mbar_wait(m ? mb1_l : mb0_l, par);  // peer acts visible
        if (tid == 0)  // re-arm this barrier for step s+2 (ordered before
            mbar_expect_tx(m ? mb1_l : mb0_l, 1024);  // s+1 sends by the
                                                      // end-of-step bar)
        if (tid < 128) {
            const float* A = &act_all[m][0];
            float iv = A[tid];
            float fv = A[128 + tid];
            float gv = A[256 + tid];
            float ov = A[384 + tid];
            creg = fv * cfd + iv * gv;      // dec already folded into cfd
            float tc;
            TANH_APPROX(tc, creg);
            float hv = ov * tc;
            hlast = hv;
            hbuf[cur ^ 1][tid] = hv;
            out[(size_t)t * (BB * HH) + (size_t)batch * HH + tid] = hv;
        }
        __syncthreads();   // h published; also orders re-arm before s+1 sends
    }

    // final state: h then c after the outputs block (rank0 only; rank1's
    // redundant out[] writes above are bit-identical so either may win)
    if (rank == 0 && tid < 128) {
        size_t base = (size_t)SS * BB * HH;
        out[base + (size_t)batch * HH + tid] = hlast;
        out[base + (size_t)BB * HH + (size_t)batch * HH + tid] = creg;
    }

    cluster_sync_hw();   // no early exit while peer ops in flight
}

// ---------------------------------------------------------------------------
// Launch
// ---------------------------------------------------------------------------
extern "C" void kernel_launch(void* const* d_in, const int* in_sizes, int n_in,
                              void* d_out, int out_size)
{
    const float* X    = (const float*)d_in[0];  // input  (S,B,D)
    const float* Tm   = (const float*)d_in[1];  // time   (S,B,1)
    const float* Wih  = (const float*)d_in[2];  // (4H, D)
    const float* Whh  = (const float*)d_in[3];  // (4H, H)
    const float* bias = (const float*)d_in[4];  // (4H,)
    const float* wt   = (const float*)d_in[5];  // (H,)
    const float* bt   = (const float*)d_in[6];  // (H,)
    float* out = (float*)d_out;

    const int smemP = 2 * 16384 * (int)sizeof(uint32_t);   // 131072 B
    cudaFuncSetAttribute(pre_gemm_kernel,
                         cudaFuncAttributeMaxDynamicSharedMemorySize, smemP);

    // x = col block (4, fastest) so consecutive CTAs reuse the same X tile
    dim3 gridP(GG / 128, (SS * BB) / 128);
    pre_gemm_kernel<<<gridP, 256, smemP>>>(X, Wih, bias);

    // 64 clusters of 2 CTAs (grid 128), 256 threads each
    lstm_rev_cluster_kernel<<<BB * 2, 256>>>(Tm, Whh, wt, bt, out);
}

// round 16
// speedup vs baseline: 1.1200x; 1.0797x over previous
#include <cuda_runtime.h>
#include <cuda_bf16.h>
#include <cstddef>
#include <cstdint>

// Problem constants
#define SS 2048
#define BB 64
#define DD 128
#define HH 128
#define GG 512   // 4*H

// 256 MB scratch for precomputed input gates: pre[t][b][512] = x@W_ih^T + b
__device__ float g_pre[(size_t)SS * BB * GG];

typedef unsigned long long ull;

// Packed fp32x2 ops (sm_100+)
#define FMA_F32X2(d, a, b, c) \
    asm("fma.rn.f32x2 %0, %1, %2, %3;" : "=l"(d) : "l"(a), "l"(b), "l"(c))
#define ADD_F32X2(d, a, b) \
    asm("add.rn.f32x2 %0, %1, %2;" : "=l"(d) : "l"(a), "l"(b))
#define UNPACK2(lo, hi, in) \
    asm("mov.b64 {%0, %1}, %2;" : "=f"(lo), "=f"(hi) : "l"(in))
// Single-instruction tanh (MUFU.TANH, sm_75+)
#define TANH_APPROX(d, x) \
    asm("tanh.approx.f32 %0, %1;" : "=f"(d) : "f"(x))
// fp32 -> tf32 bits (round to nearest)
#define CVT_TF32(out, in) \
    asm("cvt.rna.tf32.f32 %0, %1;" : "=r"(out) : "f"(in))

// ---------------------------------------------------------------------------
// Kernel P: pre = X @ W_ih^T + bias via tf32 mma.sync.m16n8k8.
// R16: 256-row x 128-col tiles, 512 threads (16 warps x 16 rows).
// Halves the wave count (4096 -> 2048 CTAs at 1 CTA/SM) on a wave-latency-
// bound kernel; staging is R13's scalar scheme with adapted loop bounds.
//   As[w][k8][lane][4]  (w: 16 warps)  -> one LDS.128 per A fragment
//   Bs[n8][k8][lane][2]                -> one LDS.64  per B fragment
// ---------------------------------------------------------------------------
__global__ void __launch_bounds__(512) pre_gemm_kernel(
    const float* __restrict__ X,
    const float* __restrict__ Wih,
    const float* __restrict__ bias)
{
    extern __shared__ uint32_t smP[];
    uint32_t* As = smP;                 // 16*16*32*4 = 32768 u32 = 128 KB
    uint32_t* Bs = smP + 32768;         // 16*16*32*2 = 16384 u32 = 64 KB

    const int tid  = threadIdx.x;
    const int row0 = blockIdx.x * 256;
    const int col0 = blockIdx.y * 128;

    // ---- stage A (X tile, 256x128) in fragment order, tf32 ----
    #pragma unroll
    for (int it = 0; it < 64; it++) {
        int idx = it * 512 + tid;
        int m = idx >> 7;          // 0..255 (row within tile)
        int k = idx & 127;         // 0..127
        float v = X[(size_t)(row0 + m) * DD + k];
        uint32_t tv;
        CVT_TF32(tv, v);
        int w    = m >> 4, mr = m & 15;    // w: 0..15
        int k8   = k >> 3, kc = k & 7;
        int lane = ((mr & 7) << 2) | (kc & 3);
        int j    = (mr >> 3) | ((kc >> 2) << 1);   // a0,a1,a2,a3 order
        As[(((w * 16 + k8) * 32) + lane) * 4 + j] = tv;
    }
    // ---- stage B (Wih tile, 128x128) in fragment order ----
    #pragma unroll
    for (int it = 0; it < 32; it++) {
        int idx = it * 512 + tid;
        int n = idx >> 7;          // 0..127 (output col within tile)
        int k = idx & 127;
        float v = Wih[(size_t)(col0 + n) * DD + k];
        uint32_t tv;
        CVT_TF32(tv, v);
        int n8   = n >> 3, nc = n & 7;
        int k8   = k >> 3, kc = k & 7;
        int lane = (nc << 2) | (kc & 3);
        int j    = kc >> 2;                         // b0,b1 order
        Bs[(((n8 * 16 + k8) * 32) + lane) * 2 + j] = tv;
    }
    __syncthreads();

    const int warp = tid >> 5;    // 0..15, warp handles rows 16w..16w+15
    const int lane = tid & 31;

    float c[16][4];
    #pragma unroll
    for (int n8 = 0; n8 < 16; n8++)
        #pragma unroll
        for (int j = 0; j < 4; j++) c[n8][j] = 0.0f;

    #pragma unroll 1
    for (int k8 = 0; k8 < 16; k8++) {
        uint4 af = *(const uint4*)&As[(((warp * 16 + k8) * 32) + lane) * 4];
        #pragma unroll
        for (int n8 = 0; n8 < 16; n8++) {
            uint2 bf = *(const uint2*)&Bs[(((n8 * 16 + k8) * 32) + lane) * 2];
            asm("mma.sync.aligned.m16n8k8.row.col.f32.tf32.tf32.f32 "
                "{%0,%1,%2,%3}, {%4,%5,%6,%7}, {%8,%9}, {%0,%1,%2,%3};"
                : "+f"(c[n8][0]), "+f"(c[n8][1]), "+f"(c[n8][2]), "+f"(c[n8][3])
                : "r"(af.x), "r"(af.y), "r"(af.z), "r"(af.w),
                  "r"(bf.x), "r"(bf.y));
        }
    }

    // ---- epilogue: bias + store ----
    // C frag: c0,c1 -> (row = lane/4,     cols 2q, 2q+1), q = lane&3
    //         c2,c3 -> (row = lane/4 + 8, same cols)
    const int ra = row0 + warp * 16 + (lane >> 2);
    const int cb = 2 * (lane & 3);
    #pragma unroll
    for (int n8 = 0; n8 < 16; n8++) {
        int col = col0 + n8 * 8 + cb;
        float2 bv = *(const float2*)&bias[col];
        float2 v0 = make_float2(c[n8][0] + bv.x, c[n8][1] + bv.y);
        float2 v1 = make_float2(c[n8][2] + bv.x, c[n8][3] + bv.y);
        *(float2*)&g_pre[(size_t)ra * GG + col]       = v0;
        *(float2*)&g_pre[(size_t)(ra + 8) * GG + col] = v1;
    }
}

// ---------------------------------------------------------------------------
// Cluster helpers
// ---------------------------------------------------------------------------
__device__ __forceinline__ uint32_t smem_u32(const void* p) {
    uint32_t a;
    asm("{ .reg .u64 t; cvta.to.shared.u64 t, %1; cvt.u32.u64 %0, t; }"
        : "=r"(a) : "l"(p));
    return a;
}
__device__ __forceinline__ uint32_t my_ctarank() {
    uint32_t r;
    asm("mov.u32 %0, %%cluster_ctarank;" : "=r"(r));
    return r;
}
__device__ __forceinline__ uint32_t mapa_u32(uint32_t local, uint32_t rank) {
    uint32_t r;
    asm("mapa.shared::cluster.u32 %0, %1, %2;" : "=r"(r) : "r"(local), "r"(rank));
    return r;
}
__device__ __forceinline__ void mbar_init(uint32_t addr, uint32_t count) {
    asm volatile("mbarrier.init.shared.b64 [%0], %1;"
                 :: "r"(addr), "r"(count) : "memory");
}
// Async store with HW transaction tracking (data + signal, no fences).
__device__ __forceinline__ void st_async_f32(uint32_t dst, float v, uint32_t mbar) {
    asm volatile(
        "st.async.shared::cluster.mbarrier::complete_tx::bytes.b32 [%0], %1, [%2];"
        :: "r"(dst), "r"(__float_as_uint(v)), "r"(mbar) : "memory");
}
__device__ __forceinline__ void mbar_expect_tx(uint32_t mbar, uint32_t bytes) {
    asm volatile("mbarrier.arrive.expect_tx.shared.b64 _, [%0], %1;"
                 :: "r"(mbar), "r"(bytes) : "memory");
}
__device__ __forceinline__ void mbar_wait(uint32_t mbar, uint32_t parity) {
    asm volatile(
        "{\n\t"
        ".reg .pred P;\n"
        "WL_%=:\n\t"
        "mbarrier.try_wait.parity.acquire.cta.shared::cta.b64 P, [%0], %1, 0x989680;\n\t"
        "@P bra WD_%=;\n\t"
        "bra WL_%=;\n"
        "WD_%=:\n\t"
        "}"
        :: "r"(mbar), "r"(parity) : "memory");
}
__device__ __forceinline__ void cluster_sync_hw() {
    asm volatile("barrier.cluster.arrive.aligned;" ::: "memory");
    asm volatile("barrier.cluster.wait.aligned;" ::: "memory");
}

// ---------------------------------------------------------------------------
// Kernel R: reverse scan, one 2-CTA CLUSTER per batch element (R10/R13
// winner, verbatim). rank0 owns gate rows 0:256 (i,f); rank1 owns 256:512
// (g,o). 256 thr/CTA, ALL 128 W_hh weights per thread register-resident.
// STS local + st.async to peer; pre-wait __syncthreads publishes local acts
// under the peer DSMEM flight; hoisted decay off the post-wait tail.
// ---------------------------------------------------------------------------
__global__ void __launch_bounds__(256, 1) __cluster_dims__(2, 1, 1)
lstm_rev_cluster_kernel(
    const float* __restrict__ timeArr,   // [S*B]
    const float* __restrict__ Whh,       // [512,128]
    const float* __restrict__ w_t,       // [128]
    const float* __restrict__ b_t,       // [128]
    float* __restrict__ out)             // outputs ++ h ++ c
{
    __shared__ __align__(16) float hbuf[2][128];
    __shared__ float act_all[2][512];
    __shared__ ull   mbars[2];

    const int tid   = threadIdx.x;
    const uint32_t rank  = my_ctarank();
    const uint32_t prank = 1u - rank;
    const int batch = blockIdx.x >> 1;
    const int grow  = (int)rank * 256 + tid;   // global gate row

    // ALL weights register-resident: 64 ull = 128 floats
    ull wR[64];
    {
        const ull* wp = (const ull*)(Whh + (size_t)grow * HH);
        #pragma unroll
        for (int c = 0; c < 64; c++) wR[c] = wp[c];
    }

    // Cluster-space addresses: my act slot in the PEER CTA + peer's mbars
    const uint32_t mb0_l = smem_u32(&mbars[0]);
    const uint32_t mb1_l = smem_u32(&mbars[1]);
    uint32_t dst_peer[2], mb_peer[2];
    #pragma unroll
    for (int m = 0; m < 2; m++) {
        uint32_t a = smem_u32(&act_all[m][grow]);
        dst_peer[m] = mapa_u32(a, prank);
        uint32_t mb = (m == 0) ? mb0_l : mb1_l;
        mb_peer[m]  = mapa_u32(mb, prank);
    }

    if (tid == 0) {
        mbar_init(mb0_l, 1);
        mbar_init(mb1_l, 1);
        // pre-arm both barriers for steps 0 and 1 (peer's 256 floats each)
        mbar_expect_tx(mb0_l, 1024);
        mbar_expect_tx(mb1_l, 1024);
    }
    if (tid < 128) hbuf[0][tid] = 0.0f;

    const float wt = w_t[tid & 127];
    const float bt = b_t[tid & 127];
    float creg = 0.0f, hlast = 0.0f;

    __syncthreads();
    cluster_sync_hw();   // mbars init+armed visible cluster-wide

    const float* preP = g_pre + (size_t)batch * GG + grow;

    // depth-2 prefetch pipeline for pre/tv
    float pre_n1 = preP[(size_t)(SS - 1) * BB * GG];
    float tv_n1  = timeArr[(size_t)(SS - 1) * BB + batch];
    float pre_n2 = preP[(size_t)(SS - 2) * BB * GG];
    float tv_n2  = timeArr[(size_t)(SS - 2) * BB + batch];

    const bool  is_g     = (rank == 1) && (tid < 128);
    // tanh path: g-gate uses tanh(x) directly; sigmoid = 0.5*tanh(x/2)+0.5
    const float pre_mul  = is_g ? 1.0f : 0.5f;

    for (int s = 0; s < SS; s++) {
        const int t   = SS - 1 - s;
        const int cur = s & 1;
        const int m   = s & 1;
        const uint32_t par = (uint32_t)((s >> 1) & 1);

        const float pre_j = pre_n1;
        const float tv    = tv_n1;
        pre_n1 = pre_n2;
        tv_n1  = tv_n2;
        if (t >= 2) {   // prefetch two steps ahead
            pre_n2 = preP[(size_t)(t - 2) * BB * GG];
            tv_n2  = timeArr[(size_t)(t - 2) * BB + batch];
        }

        // dot: gates[grow] = pre + W_hh[grow].h  (weights in regs,
        // 8 independent accumulator chains)
        const ulonglong2* h2 = (const ulonglong2*)&hbuf[cur][0];
        ull ac[8];
        #pragma unroll
        for (int i = 0; i < 8; i++) ac[i] = 0ULL;
        #pragma unroll
        for (int i = 0; i < 8; i++) {
            ulonglong2 hva = h2[4 * i],     hvb = h2[4 * i + 1];
            ulonglong2 hvc = h2[4 * i + 2], hvd = h2[4 * i + 3];
            FMA_F32X2(ac[0], wR[8 * i],     hva.x, ac[0]);
            FMA_F32X2(ac[1], wR[8 * i + 1], hva.y, ac[1]);
            FMA_F32X2(ac[2], wR[8 * i + 2], hvb.x, ac[2]);
            FMA_F32X2(ac[3], wR[8 * i + 3], hvb.y, ac[3]);
            FMA_F32X2(ac[4], wR[8 * i + 4], hvc.x, ac[4]);
            FMA_F32X2(ac[5], wR[8 * i + 5], hvc.y, ac[5]);
            FMA_F32X2(ac[6], wR[8 * i + 6], hvd.x, ac[6]);
            FMA_F32X2(ac[7], wR[8 * i + 7], hvd.y, ac[7]);
        }
        ADD_F32X2(ac[0], ac[0], ac[1]);
        ADD_F32X2(ac[2], ac[2], ac[3]);
        ADD_F32X2(ac[4], ac[4], ac[5]);
        ADD_F32X2(ac[6], ac[6], ac[7]);
        ADD_F32X2(ac[0], ac[0], ac[2]);
        ADD_F32X2(ac[4], ac[4], ac[6]);
        ADD_F32X2(ac[0], ac[0], ac[4]);
        float lo, hi;
        UNPACK2(lo, hi, ac[0]);
        float gsum = pre_j + (lo + hi);

        // activation via single MUFU.TANH:
        //   g-gate: tanh(gsum);  others: sigmoid = 0.5*tanh(0.5*gsum)+0.5
        float th;
        TANH_APPROX(th, pre_mul * gsum);
        float a = is_g ? th : fmaf(0.5f, th, 0.5f);

        // publish act: plain STS locally, st.async to PEER only
        act_all[m][grow] = a;
        st_async_f32(dst_peer[m], a, mb_peer[m]);

        // decay term hoisted off the post-wait critical path
        float cfd = 0.0f;
        if (tid < 128) {
            float dec = __expf(-fmaxf(tv * wt + bt, 0.0f));
            cfd = creg * dec;
        }

        __syncthreads();                    // local acts visible (overlaps
                                            // the peer DSMEM flight)
        mbar_wait(m ? mb1_l : mb0_l, par);  // peer acts visible
        if (tid == 0)  // re-arm this barrier for step s+2 (ordered before
            mbar_expect_tx(m ? mb1_l : mb0_l, 1024);  // s+1 sends by the
                                                      // end-of-step bar)
        if (tid < 128) {
            const float* A = &act_all[m][0];
            float iv = A[tid];
            float fv = A[128 + tid];
            float gv = A[256 + tid];
            float ov = A[384 + tid];
            creg = fv * cfd + iv * gv;      // dec already folded into cfd
            float tc;
            TANH_APPROX(tc, creg);
            float hv = ov * tc;
            hlast = hv;
            hbuf[cur ^ 1][tid] = hv;
            out[(size_t)t * (BB * HH) + (size_t)batch * HH + tid] = hv;
        }
        __syncthreads();   // h published; also orders re-arm before s+1 sends
    }

    // final state: h then c after the outputs block (rank0 only; rank1's
    // redundant out[] writes above are bit-identical so either may win)
    if (rank == 0 && tid < 128) {
        size_t base = (size_t)SS * BB * HH;
        out[base + (size_t)batch * HH + tid] = hlast;
        out[base + (size_t)BB * HH + (size_t)batch * HH + tid] = creg;
    }

    cluster_sync_hw();   // no early exit while peer ops in flight
}

// ---------------------------------------------------------------------------
// Launch
// ---------------------------------------------------------------------------
extern "C" void kernel_launch(void* const* d_in, const int* in_sizes, int n_in,
                              void* d_out, int out_size)
{
    const float* X    = (const float*)d_in[0];  // input  (S,B,D)
    const float* Tm   = (const float*)d_in[1];  // time   (S,B,1)
    const float* Wih  = (const float*)d_in[2];  // (4H, D)
    const float* Whh  = (const float*)d_in[3];  // (4H, H)
    const float* bias = (const float*)d_in[4];  // (4H,)
    const float* wt   = (const float*)d_in[5];  // (H,)
    const float* bt   = (const float*)d_in[6];  // (H,)
    float* out = (float*)d_out;

    const int smemP = (32768 + 16384) * (int)sizeof(uint32_t);   // 196608 B
    cudaFuncSetAttribute(pre_gemm_kernel,
                         cudaFuncAttributeMaxDynamicSharedMemorySize, smemP);

    // 256-row tiles: grid (512, 4), 512 threads
    dim3 gridP((SS * BB) / 256, GG / 128);
    pre_gemm_kernel<<<gridP, 512, smemP>>>(X, Wih, bias);

    // 64 clusters of 2 CTAs (grid 128), 256 threads each
    lstm_rev_cluster_kernel<<<BB * 2, 256>>>(Tm, Whh, wt, bt, out);
}